// round 14
// baseline (speedup 1.0000x reference)
#include <cuda_runtime.h>
#include <cstdint>
#include <mma.h>
using namespace nvcuda;

// Problem constants
#define BB   8
#define SS   4096
#define DD   256
#define NW   8
#define WINS 512
#define HH   2
#define KD   256
#define DFF  1024
#define MTOK (BB*SS)          // 32768 tokens

// ---------------- device scratch (static allocation; no cudaMalloc) -------
__device__ float g_q  [(size_t)BB*SS*HH*KD];   // [b,w,h,s,k]
__device__ float g_k  [(size_t)BB*SS*HH*KD];
__device__ float g_v  [(size_t)BB*SS*HH*KD];
__device__ float g_ctx[(size_t)BB*SS*HH*KD];   // [token, h*K+k]
__device__ float g_y  [(size_t)MTOK*DD];       // post-LN1
__device__ float g_h  [(size_t)MTOK*DFF];      // FFN hidden

// ---------------- cp.async helpers -----------------------------------------
__device__ __forceinline__ void cpa16(float* smem, const float* g) {
    unsigned s = (unsigned)__cvta_generic_to_shared(smem);
    asm volatile("cp.async.cg.shared.global [%0], [%1], 16;" :: "r"(s), "l"(g));
}
#define CPA_COMMIT() asm volatile("cp.async.commit_group;")
#define CPA_WAIT1()  asm volatile("cp.async.wait_group 1;")
#define CPA_WAIT0()  asm volatile("cp.async.wait_group 0;")

// ---------------- tf32 wmma GEMM: block 64x256, warp tile 32x64 -------------
// C[M,N] = A[M,Kd] @ B[Kd,N] + bias[N]
// EPI: 0 plain, 1 relu, 2 qkv-scatter, 3 residual+LayerNorm (needs N==256)
// 8 warps in 2x4 grid; 2-stage cp.async; 85KB smem -> 2 CTAs/SM (16 warps).
#define GSTG  10624                   // floats/stage: A 64*36 + B 32*260
#define GEMM_SMEM (2*GSTG*4)          // 84,992 B

template<int EPI>
__device__ __forceinline__
void gemm_body(const float* __restrict__ A, const float* __restrict__ Bm,
               const float* __restrict__ bias, float* __restrict__ C,
               int N, int Kd, float* sg,
               const float* __restrict__ resid,
               const float* __restrict__ lng,
               const float* __restrict__ lnb)
{
    const int m0 = blockIdx.y * 64;
    const int n0 = blockIdx.x * 256;
    const int tid = threadIdx.x;
    const int wid = tid >> 5;
    const int lane = tid & 31;
    const int wr = wid >> 2;     // 0..1 -> 32-row group
    const int wc = wid & 3;      // 0..3 -> 64-col group

    const int ar = tid >> 3, ac = (tid & 7) * 4;     // A: 64x32, 2 float4/thr

    wmma::fragment<wmma::accumulator, 16, 16, 8, float> acc[2][4];
#pragma unroll
    for (int i = 0; i < 2; i++)
#pragma unroll
        for (int j = 0; j < 4; j++) wmma::fill_fragment(acc[i][j], 0.f);

    const int nk = Kd >> 5;

    auto load_stage = [&](int s, int k0) {
        float* As = sg + s * GSTG;
        float* Bs = As + 2304;
#pragma unroll
        for (int it = 0; it < 2; it++)
            cpa16(&As[(ar + it * 32) * 36 + ac],
                  &A[(size_t)(m0 + ar + it * 32) * Kd + k0 + ac]);
#pragma unroll
        for (int it = 0; it < 8; it++) {             // B: 32x256, 8 float4/thr
            int lin = tid + it * 256;
            int r = lin >> 6, c = (lin & 63) * 4;
            cpa16(&Bs[r * 260 + c],
                  &Bm[(size_t)(k0 + r) * N + n0 + c]);
        }
    };

    load_stage(0, 0);  CPA_COMMIT();
    load_stage(1, 32); CPA_COMMIT();

    for (int c = 0; c < nk; c++) {
        if (c + 1 < nk) { CPA_WAIT1(); } else { CPA_WAIT0(); }
        __syncthreads();
        float* As = sg + (c & 1) * GSTG;
        float* Bs = As + 2304;
#pragma unroll
        for (int kk = 0; kk < 4; kk++) {
            wmma::fragment<wmma::matrix_a, 16, 16, 8, wmma::precision::tf32, wmma::row_major> af[2];
#pragma unroll
            for (int i = 0; i < 2; i++)
                wmma::load_matrix_sync(af[i], &As[(wr * 32 + i * 16) * 36 + kk * 8], 36);
#pragma unroll
            for (int j = 0; j < 4; j++) {
                wmma::fragment<wmma::matrix_b, 16, 16, 8, wmma::precision::tf32, wmma::row_major> bf;
                wmma::load_matrix_sync(bf, &Bs[(kk * 8) * 260 + wc * 64 + j * 16], 260);
#pragma unroll
                for (int i = 0; i < 2; i++)
                    wmma::mma_sync(acc[i][j], af[i], bf, acc[i][j]);
            }
        }
        __syncthreads();
        if (c + 2 < nk) { load_stage(c & 1, (c + 2) * 32); CPA_COMMIT(); }
    }

    // epilogue: single 64-row tile staged through smem (64 x 264)
    float* se = sg;
#pragma unroll
    for (int i = 0; i < 2; i++)
#pragma unroll
        for (int j = 0; j < 4; j++)
            wmma::store_matrix_sync(&se[(wr * 32 + i * 16) * 264 + wc * 64 + j * 16],
                                    acc[i][j], 264, wmma::mem_row_major);
    __syncthreads();

    if (EPI == 3) {
        // residual + LayerNorm over full 256-wide rows; warp w -> rows w*8..w*8+7
#pragma unroll
        for (int rr = 0; rr < 8; rr++) {
            int r = wid * 8 + rr;                // 0..63
            size_t row = (size_t)(m0 + r);
            float vv[8];
            float s = 0.f;
#pragma unroll
            for (int j = 0; j < 8; j++) {
                int cc = lane + j * 32;
                vv[j] = se[r * 264 + cc] + bias[cc] + resid[row * DD + cc];
                s += vv[j];
            }
#pragma unroll
            for (int o = 16; o; o >>= 1) s += __shfl_xor_sync(0xffffffffu, s, o);
            float mu = s * (1.f / 256.f);
            float vs = 0.f;
#pragma unroll
            for (int j = 0; j < 8; j++) {
                float d = vv[j] - mu;
                vs += d * d;
            }
#pragma unroll
            for (int o = 16; o; o >>= 1) vs += __shfl_xor_sync(0xffffffffu, vs, o);
            float inv = rsqrtf(vs * (1.f / 256.f) + 1e-3f);
#pragma unroll
            for (int j = 0; j < 8; j++) {
                int cc = lane + j * 32;
                C[row * DD + cc] = (vv[j] - mu) * inv * lng[cc] + lnb[cc];
            }
        }
    } else {
#pragma unroll
        for (int it = 0; it < 16; it++) {
            int lin = tid + it * 256;           // 0..4095 quads (64x256 elems)
            int r = lin >> 6, c4 = (lin & 63) * 4;
            int row = m0 + r, col = n0 + c4;
            float4 cv;
            cv.x = se[r * 264 + c4 + 0] + bias[col + 0];
            cv.y = se[r * 264 + c4 + 1] + bias[col + 1];
            cv.z = se[r * 264 + c4 + 2] + bias[col + 2];
            cv.w = se[r * 264 + c4 + 3] + bias[col + 3];
            if (EPI == 1) {
                cv.x = fmaxf(cv.x, 0.f); cv.y = fmaxf(cv.y, 0.f);
                cv.z = fmaxf(cv.z, 0.f); cv.w = fmaxf(cv.w, 0.f);
            }
            if (EPI == 2) {
                int b_ = row >> 12, sgx = row & 4095;
                int w  = sgx >> 9,  sl = sgx & 511;
                int hh = col >> 8,  kd = col & 255;
                size_t idx = (((size_t)((b_ * NW + w) * HH + hh)) * WINS + sl) * KD + kd;
                *(float4*)&C[idx] = cv;
            } else {
                *(float4*)&C[(size_t)row * N + col] = cv;
            }
        }
    }
    __syncthreads();
}

template<int EPI>
__global__ __launch_bounds__(256, 2)
void gemm_tc(const float* __restrict__ A, const float* __restrict__ Bm,
             const float* __restrict__ bias, float* __restrict__ C,
             int N, int Kd,
             const float* resid, const float* lng, const float* lnb)
{
    extern __shared__ float sg[];
    gemm_body<EPI>(A, Bm, bias, C, N, Kd, sg, resid, lng, lnb);
}

// fused QKV: grid.z selects {q,k,v}
__global__ __launch_bounds__(256, 2)
void qkv_tc(const float* __restrict__ x,
            const float* __restrict__ Wq, const float* __restrict__ Wk,
            const float* __restrict__ Wv,
            const float* __restrict__ bq, const float* __restrict__ bk,
            const float* __restrict__ bv)
{
    extern __shared__ float sg[];
    int z = blockIdx.z;
    const float* Bm  = (z == 0) ? Wq : (z == 1) ? Wk : Wv;
    const float* bia = (z == 0) ? bq : (z == 1) ? bk : bv;
    float* C = (z == 0) ? g_q : (z == 1) ? g_k : g_v;
    gemm_body<2>(x, Bm, bia, C, HH * KD, DD, sg, nullptr, nullptr, nullptr);
}

// ---------------- windowed attention (tensor-core, 32-query tiles) ----------
// grid: (WIN/32 = 16, B*NW*H = 128), 256 threads (8 warps)
// smem: sS[32][516] | sK[512][20] | sQc[32][20]
// phase 2: per-warp double-buffered V tiles (8 warps x 2 x 16x36) alias sK.
#define SMEM_ATTN ((32*516 + 512*20 + 32*20) * 4)

__global__ __launch_bounds__(256, 2)
void attn_tc(const float* __restrict__ q, const float* __restrict__ k,
             const float* __restrict__ v, float* __restrict__ ctx)
{
    extern __shared__ float sm[];
    float* sS  = sm;                     // 32 x 516
    float* sK  = sm + 32 * 516;          // 512 x 20
    float* sQc = sK + 512 * 20;          // 32 x 20

    const int bwh = blockIdx.y;
    const int m0  = blockIdx.x * 32;
    const size_t base = (size_t)bwh * WINS * KD;
    const int tid = threadIdx.x;
    const int wid = tid >> 5;
    const int lane = tid & 31;

    // ---- phase 1: S = Q K^T / 16; warp tile 32 rows x 64 cols ----
    {
        wmma::fragment<wmma::accumulator, 16, 16, 8, float> acc[2][4];
#pragma unroll
        for (int i = 0; i < 2; i++)
#pragma unroll
            for (int j = 0; j < 4; j++) wmma::fill_fragment(acc[i][j], 0.f);

        for (int kc = 0; kc < 16; kc++) {           // 16-dim chunks of KD
            if (tid < 128) {
                int r = tid >> 2, c4 = (tid & 3) * 4;
                float4 f = *(const float4*)&q[base + (size_t)(m0 + r) * KD + kc * 16 + c4];
                *(float4*)&sQc[r * 20 + c4] = f;
            }
#pragma unroll
            for (int it = 0; it < 8; it++) {
                int lin = tid + it * 256;
                int r = lin >> 2, c4 = (lin & 3) * 4;
                float4 f = *(const float4*)&k[base + (size_t)r * KD + kc * 16 + c4];
                *(float4*)&sK[r * 20 + c4] = f;
            }
            __syncthreads();
#pragma unroll
            for (int kk = 0; kk < 2; kk++) {
                wmma::fragment<wmma::matrix_a, 16, 16, 8, wmma::precision::tf32, wmma::row_major> af[2];
#pragma unroll
                for (int i = 0; i < 2; i++)
                    wmma::load_matrix_sync(af[i], &sQc[(i * 16) * 20 + kk * 8], 20);
#pragma unroll
                for (int j = 0; j < 4; j++) {
                    wmma::fragment<wmma::matrix_b, 16, 16, 8, wmma::precision::tf32, wmma::col_major> bf;
                    wmma::load_matrix_sync(bf, &sK[(wid * 64 + j * 16) * 20 + kk * 8], 20);
#pragma unroll
                    for (int i = 0; i < 2; i++)
                        wmma::mma_sync(acc[i][j], af[i], bf, acc[i][j]);
                }
            }
            __syncthreads();
        }
#pragma unroll
        for (int i = 0; i < 2; i++)
#pragma unroll
            for (int j = 0; j < 4; j++) {
#pragma unroll
                for (int t = 0; t < acc[i][j].num_elements; t++) acc[i][j].x[t] *= 0.0625f;
                wmma::store_matrix_sync(&sS[(i * 16) * 516 + wid * 64 + j * 16],
                                        acc[i][j], 516, wmma::mem_row_major);
            }
    }
    __syncthreads();

    // ---- softmax: 8 warps x 4 rows ----
#pragma unroll
    for (int rr = 0; rr < 4; rr++) {
        int r = wid * 4 + rr;
        float mx = -1e30f;
        for (int c = lane; c < 512; c += 32) mx = fmaxf(mx, sS[r * 516 + c]);
#pragma unroll
        for (int o = 16; o; o >>= 1) mx = fmaxf(mx, __shfl_xor_sync(0xffffffffu, mx, o));
        float sum = 0.f;
        for (int c = lane; c < 512; c += 32) {
            float e = expf(sS[r * 516 + c] - mx);
            sS[r * 516 + c] = e;
            sum += e;
        }
#pragma unroll
        for (int o = 16; o; o >>= 1) sum += __shfl_xor_sync(0xffffffffu, sum, o);
        float inv = 1.f / sum;
        for (int c = lane; c < 512; c += 32) sS[r * 516 + c] *= inv;
    }
    __syncthreads();   // scores final; sK region free for per-warp V tiles

    // ---- phase 2: ctx = P @ V; warp tile 32 rows x 32 cols ----
    {
        float* sVw = sK + wid * (2 * 576);   // 2 buffers of 16x36

        wmma::fragment<wmma::accumulator, 16, 16, 8, float> acc2[2][2];
#pragma unroll
        for (int i = 0; i < 2; i++)
#pragma unroll
            for (int j = 0; j < 2; j++) wmma::fill_fragment(acc2[i][j], 0.f);

        auto stage_v = [&](int kc) {
            float* dst = sVw + (kc & 1) * 576;
#pragma unroll
            for (int it = 0; it < 4; it++) {
                int lin = lane + it * 32;
                int r = lin >> 3, c4 = (lin & 7) * 4;
                cpa16(&dst[r * 36 + c4],
                      &v[base + (size_t)(kc * 16 + r) * KD + wid * 32 + c4]);
            }
        };

        stage_v(0); CPA_COMMIT();

        for (int kc = 0; kc < 32; kc++) {
            if (kc + 1 < 32) { stage_v(kc + 1); CPA_COMMIT(); CPA_WAIT1(); }
            else             { CPA_WAIT0(); }
            __syncwarp();
            float* sVc = sVw + (kc & 1) * 576;
#pragma unroll
            for (int kk = 0; kk < 2; kk++) {
                wmma::fragment<wmma::matrix_a, 16, 16, 8, wmma::precision::tf32, wmma::row_major> af[2];
#pragma unroll
                for (int i = 0; i < 2; i++)
                    wmma::load_matrix_sync(af[i], &sS[(i * 16) * 516 + kc * 16 + kk * 8], 516);
#pragma unroll
                for (int j = 0; j < 2; j++) {
                    wmma::fragment<wmma::matrix_b, 16, 16, 8, wmma::precision::tf32, wmma::row_major> bf;
                    wmma::load_matrix_sync(bf, &sVc[(kk * 8) * 36 + j * 16], 36);
#pragma unroll
                    for (int i = 0; i < 2; i++)
                        wmma::mma_sync(acc2[i][j], af[i], bf, acc2[i][j]);
                }
            }
            __syncwarp();
        }

        const int b_ = bwh >> 4, w = (bwh >> 1) & 7, h = bwh & 1;
        const size_t tok0 = (size_t)b_ * SS + w * WINS + m0;
#pragma unroll
        for (int i = 0; i < 2; i++)
#pragma unroll
            for (int j = 0; j < 2; j++) {
                size_t row = tok0 + i * 16;
                int col = h * KD + wid * 32 + j * 16;
                wmma::store_matrix_sync(&ctx[row * (HH * KD) + col], acc2[i][j],
                                        HH * KD, wmma::mem_row_major);
            }
    }
}

// ---------------- launch ----------------------------------------------------
extern "C" void kernel_launch(void* const* d_in, const int* in_sizes, int n_in,
                              void* d_out, int out_size)
{
    const float* x    = (const float*)d_in[0];
    const float* Wq   = (const float*)d_in[1];
    const float* bq   = (const float*)d_in[2];
    const float* Wk   = (const float*)d_in[3];
    const float* bk   = (const float*)d_in[4];
    const float* Wv   = (const float*)d_in[5];
    const float* bv   = (const float*)d_in[6];
    const float* Wo   = (const float*)d_in[7];
    const float* bo   = (const float*)d_in[8];
    const float* ln1g = (const float*)d_in[9];
    const float* ln1b = (const float*)d_in[10];
    const float* W1   = (const float*)d_in[11];
    const float* b1   = (const float*)d_in[12];
    const float* W2   = (const float*)d_in[13];
    const float* b2   = (const float*)d_in[14];
    const float* ln2g = (const float*)d_in[15];
    const float* ln2b = (const float*)d_in[16];

    float *q, *k, *v, *ctx, *y, *hbuf;
    cudaGetSymbolAddress((void**)&q,    g_q);
    cudaGetSymbolAddress((void**)&k,    g_k);
    cudaGetSymbolAddress((void**)&v,    g_v);
    cudaGetSymbolAddress((void**)&ctx,  g_ctx);
    cudaGetSymbolAddress((void**)&y,    g_y);
    cudaGetSymbolAddress((void**)&hbuf, g_h);

    cudaFuncSetAttribute(attn_tc,    cudaFuncAttributeMaxDynamicSharedMemorySize, SMEM_ATTN);
    cudaFuncSetAttribute(qkv_tc,     cudaFuncAttributeMaxDynamicSharedMemorySize, GEMM_SMEM);
    cudaFuncSetAttribute(gemm_tc<1>, cudaFuncAttributeMaxDynamicSharedMemorySize, GEMM_SMEM);
    cudaFuncSetAttribute(gemm_tc<3>, cudaFuncAttributeMaxDynamicSharedMemorySize, GEMM_SMEM);

    dim3 blk(256);

    // fused QKV projections (scatter into [b,w,h,s,k]); N=512 -> 2 n-tiles
    qkv_tc<<<dim3(2, 512, 3), blk, GEMM_SMEM>>>(x, Wq, Wk, Wv, bq, bk, bv);

    // windowed attention
    attn_tc<<<dim3(16, 128), blk, SMEM_ATTN>>>(q, k, v, ctx);

    // output projection fused with residual+LN1: y = LN(ctx@Wo + bo + x)
    gemm_tc<3><<<dim3(1, 512), blk, GEMM_SMEM>>>(ctx, Wo, bo, y, DD, HH * KD,
                                                 x, ln1g, ln1b);

    // FFN: h = relu(y@W1 + b1)
    gemm_tc<1><<<dim3(4, 512), blk, GEMM_SMEM>>>(y, W1, b1, hbuf, DFF, DD,
                                                 nullptr, nullptr, nullptr);
    // out = LN(h@W2 + b2 + y)
    gemm_tc<3><<<dim3(1, 512), blk, GEMM_SMEM>>>(hbuf, W2, b2, (float*)d_out, DD, DFF,
                                                 y, ln2g, ln2b);
}

// round 15
// speedup vs baseline: 1.6528x; 1.6528x over previous
#include <cuda_runtime.h>
#include <cstdint>
#include <mma.h>
using namespace nvcuda;

// Problem constants
#define BB   8
#define SS   4096
#define DD   256
#define NW   8
#define WINS 512
#define HH   2
#define KD   256
#define DFF  1024
#define MTOK (BB*SS)          // 32768 tokens

// ---------------- device scratch (static allocation; no cudaMalloc) -------
__device__ float g_q  [(size_t)BB*SS*HH*KD];   // [b,w,h,s,k]
__device__ float g_k  [(size_t)BB*SS*HH*KD];
__device__ float g_v  [(size_t)BB*SS*HH*KD];
__device__ float g_ctx[(size_t)BB*SS*HH*KD];   // [token, h*K+k]
__device__ float g_y  [(size_t)MTOK*DD];       // post-LN1
__device__ float g_h  [(size_t)MTOK*DFF];      // FFN hidden

// ---------------- cp.async helpers -----------------------------------------
__device__ __forceinline__ void cpa16(float* smem, const float* g) {
    unsigned s = (unsigned)__cvta_generic_to_shared(smem);
    asm volatile("cp.async.cg.shared.global [%0], [%1], 16;" :: "r"(s), "l"(g));
}
#define CPA_COMMIT() asm volatile("cp.async.commit_group;")
#define CPA_WAIT2()  asm volatile("cp.async.wait_group 2;")
#define CPA_WAIT1()  asm volatile("cp.async.wait_group 1;")
#define CPA_WAIT0()  asm volatile("cp.async.wait_group 0;")

// ---------------- tf32 wmma GEMM: block 128x256, warp tile 64x64 ------------
// C[M,N] = A[M,Kd] @ B[Kd,N] + bias[N]
// EPI: 0 plain, 1 relu, 2 qkv-scatter, 3 residual+LayerNorm (needs N==256)
// 8 warps in 2x4 grid; 3-stage cp.async; 1 CTA/SM (155KB smem).
#define GSTG  12928                   // floats/stage: A 128*36 + B 32*260
#define GEMM_SMEM (3*GSTG*4)          // 155,136 B

template<int EPI>
__device__ __forceinline__
void gemm_body(const float* __restrict__ A, const float* __restrict__ Bm,
               const float* __restrict__ bias, float* __restrict__ C,
               int N, int Kd, float* sg,
               const float* __restrict__ resid,
               const float* __restrict__ lng,
               const float* __restrict__ lnb)
{
    const int m0 = blockIdx.y * 128;
    const int n0 = blockIdx.x * 256;
    const int tid = threadIdx.x;
    const int wid = tid >> 5;
    const int lane = tid & 31;
    const int wr = wid >> 2;     // 0..1 -> 64-row group
    const int wc = wid & 3;      // 0..3 -> 64-col group

    const int ar = tid >> 3, ac = (tid & 7) * 4;     // A: 128x32, 4 float4/thr

    wmma::fragment<wmma::accumulator, 16, 16, 8, float> acc[4][4];
#pragma unroll
    for (int i = 0; i < 4; i++)
#pragma unroll
        for (int j = 0; j < 4; j++) wmma::fill_fragment(acc[i][j], 0.f);

    const int nk = Kd >> 5;

    auto load_stage = [&](int s, int k0) {
        float* As = sg + s * GSTG;
        float* Bs = As + 4608;
#pragma unroll
        for (int it = 0; it < 4; it++)
            cpa16(&As[(ar + it * 32) * 36 + ac],
                  &A[(size_t)(m0 + ar + it * 32) * Kd + k0 + ac]);
#pragma unroll
        for (int it = 0; it < 8; it++) {             // B: 32x256, 8 float4/thr
            int lin = tid + it * 256;
            int r = lin >> 6, c = (lin & 63) * 4;
            cpa16(&Bs[r * 260 + c],
                  &Bm[(size_t)(k0 + r) * N + n0 + c]);
        }
    };

    load_stage(0, 0);  CPA_COMMIT();
    load_stage(1, 32); CPA_COMMIT();
    load_stage(2, 64); CPA_COMMIT();

    for (int c = 0; c < nk; c++) {
        int rem = nk - 1 - c;
        if (rem >= 2) { CPA_WAIT2(); } else if (rem == 1) { CPA_WAIT1(); } else { CPA_WAIT0(); }
        __syncthreads();
        float* As = sg + (c % 3) * GSTG;
        float* Bs = As + 4608;
#pragma unroll
        for (int kk = 0; kk < 4; kk++) {
            wmma::fragment<wmma::matrix_a, 16, 16, 8, wmma::precision::tf32, wmma::row_major> af[4];
#pragma unroll
            for (int i = 0; i < 4; i++)
                wmma::load_matrix_sync(af[i], &As[(wr * 64 + i * 16) * 36 + kk * 8], 36);
#pragma unroll
            for (int j = 0; j < 4; j++) {
                wmma::fragment<wmma::matrix_b, 16, 16, 8, wmma::precision::tf32, wmma::row_major> bf;
                wmma::load_matrix_sync(bf, &Bs[(kk * 8) * 260 + wc * 64 + j * 16], 260);
#pragma unroll
                for (int i = 0; i < 4; i++)
                    wmma::mma_sync(acc[i][j], af[i], bf, acc[i][j]);
            }
        }
        __syncthreads();
        if (c + 3 < nk) { load_stage(c % 3, (c + 3) * 32); CPA_COMMIT(); }
    }

    // epilogue: two 64-row halves staged through smem (64 x 264)
    float* se = sg;
#pragma unroll
    for (int h = 0; h < 2; h++) {
        if (wr == h) {
#pragma unroll
            for (int i = 0; i < 4; i++)
#pragma unroll
                for (int j = 0; j < 4; j++)
                    wmma::store_matrix_sync(&se[(i * 16) * 264 + wc * 64 + j * 16],
                                            acc[i][j], 264, wmma::mem_row_major);
        }
        __syncthreads();
        if (EPI == 3) {
            // residual + LayerNorm over full 256-wide rows; warp w -> rows w*8..w*8+7
#pragma unroll
            for (int rr = 0; rr < 8; rr++) {
                int r = wid * 8 + rr;                // 0..63 within half
                size_t row = (size_t)(m0 + h * 64 + r);
                float vv[8];
                float s = 0.f;
#pragma unroll
                for (int j = 0; j < 8; j++) {
                    int cc = lane + j * 32;
                    vv[j] = se[r * 264 + cc] + bias[cc] + resid[row * DD + cc];
                    s += vv[j];
                }
#pragma unroll
                for (int o = 16; o; o >>= 1) s += __shfl_xor_sync(0xffffffffu, s, o);
                float mu = s * (1.f / 256.f);
                float vs = 0.f;
#pragma unroll
                for (int j = 0; j < 8; j++) {
                    float d = vv[j] - mu;
                    vs += d * d;
                }
#pragma unroll
                for (int o = 16; o; o >>= 1) vs += __shfl_xor_sync(0xffffffffu, vs, o);
                float inv = rsqrtf(vs * (1.f / 256.f) + 1e-3f);
#pragma unroll
                for (int j = 0; j < 8; j++) {
                    int cc = lane + j * 32;
                    C[row * DD + cc] = (vv[j] - mu) * inv * lng[cc] + lnb[cc];
                }
            }
        } else {
#pragma unroll
            for (int it = 0; it < 16; it++) {
                int lin = tid + it * 256;           // 0..4095 quads (64x256 elems)
                int r = lin >> 6, c4 = (lin & 63) * 4;
                int row = m0 + h * 64 + r, col = n0 + c4;
                float4 cv;
                cv.x = se[r * 264 + c4 + 0] + bias[col + 0];
                cv.y = se[r * 264 + c4 + 1] + bias[col + 1];
                cv.z = se[r * 264 + c4 + 2] + bias[col + 2];
                cv.w = se[r * 264 + c4 + 3] + bias[col + 3];
                if (EPI == 1) {
                    cv.x = fmaxf(cv.x, 0.f); cv.y = fmaxf(cv.y, 0.f);
                    cv.z = fmaxf(cv.z, 0.f); cv.w = fmaxf(cv.w, 0.f);
                }
                if (EPI == 2) {
                    int b_ = row >> 12, sgx = row & 4095;
                    int w  = sgx >> 9,  sl = sgx & 511;
                    int hh = col >> 8,  kd = col & 255;
                    size_t idx = (((size_t)((b_ * NW + w) * HH + hh)) * WINS + sl) * KD + kd;
                    *(float4*)&C[idx] = cv;
                } else {
                    *(float4*)&C[(size_t)row * N + col] = cv;
                }
            }
        }
        __syncthreads();
    }
}

template<int EPI>
__global__ __launch_bounds__(256, 1)
void gemm_tc(const float* __restrict__ A, const float* __restrict__ Bm,
             const float* __restrict__ bias, float* __restrict__ C,
             int N, int Kd,
             const float* resid, const float* lng, const float* lnb)
{
    extern __shared__ float sg[];
    gemm_body<EPI>(A, Bm, bias, C, N, Kd, sg, resid, lng, lnb);
}

// fused QKV: grid.z selects {q,k,v}
__global__ __launch_bounds__(256, 1)
void qkv_tc(const float* __restrict__ x,
            const float* __restrict__ Wq, const float* __restrict__ Wk,
            const float* __restrict__ Wv,
            const float* __restrict__ bq, const float* __restrict__ bk,
            const float* __restrict__ bv)
{
    extern __shared__ float sg[];
    int z = blockIdx.z;
    const float* Bm  = (z == 0) ? Wq : (z == 1) ? Wk : Wv;
    const float* bia = (z == 0) ? bq : (z == 1) ? bk : bv;
    float* C = (z == 0) ? g_q : (z == 1) ? g_k : g_v;
    gemm_body<2>(x, Bm, bia, C, HH * KD, DD, sg, nullptr, nullptr, nullptr);
}

// ---------------- windowed attention (tensor-core, 32-query tiles) ----------
// grid: (WIN/32 = 16, B*NW*H = 128), 256 threads (8 warps)
// smem: sS[32][516] | sK[512][20] | sQc[32][20]
// phase 2: per-warp double-buffered V tiles (8 warps x 2 x 16x36) alias sK.
#define SMEM_ATTN ((32*516 + 512*20 + 32*20) * 4)

__global__ __launch_bounds__(256, 2)
void attn_tc(const float* __restrict__ q, const float* __restrict__ k,
             const float* __restrict__ v, float* __restrict__ ctx)
{
    extern __shared__ float sm[];
    float* sS  = sm;                     // 32 x 516
    float* sK  = sm + 32 * 516;          // 512 x 20
    float* sQc = sK + 512 * 20;          // 32 x 20

    const int bwh = blockIdx.y;
    const int m0  = blockIdx.x * 32;
    const size_t base = (size_t)bwh * WINS * KD;
    const int tid = threadIdx.x;
    const int wid = tid >> 5;
    const int lane = tid & 31;

    // ---- phase 1: S = Q K^T / 16; warp tile 32 rows x 64 cols ----
    {
        wmma::fragment<wmma::accumulator, 16, 16, 8, float> acc[2][4];
#pragma unroll
        for (int i = 0; i < 2; i++)
#pragma unroll
            for (int j = 0; j < 4; j++) wmma::fill_fragment(acc[i][j], 0.f);

        for (int kc = 0; kc < 16; kc++) {           // 16-dim chunks of KD
            if (tid < 128) {
                int r = tid >> 2, c4 = (tid & 3) * 4;
                float4 f = *(const float4*)&q[base + (size_t)(m0 + r) * KD + kc * 16 + c4];
                *(float4*)&sQc[r * 20 + c4] = f;
            }
#pragma unroll
            for (int it = 0; it < 8; it++) {
                int lin = tid + it * 256;
                int r = lin >> 2, c4 = (lin & 3) * 4;
                float4 f = *(const float4*)&k[base + (size_t)r * KD + kc * 16 + c4];
                *(float4*)&sK[r * 20 + c4] = f;
            }
            __syncthreads();
#pragma unroll
            for (int kk = 0; kk < 2; kk++) {
                wmma::fragment<wmma::matrix_a, 16, 16, 8, wmma::precision::tf32, wmma::row_major> af[2];
#pragma unroll
                for (int i = 0; i < 2; i++)
                    wmma::load_matrix_sync(af[i], &sQc[(i * 16) * 20 + kk * 8], 20);
#pragma unroll
                for (int j = 0; j < 4; j++) {
                    wmma::fragment<wmma::matrix_b, 16, 16, 8, wmma::precision::tf32, wmma::col_major> bf;
                    wmma::load_matrix_sync(bf, &sK[(wid * 64 + j * 16) * 20 + kk * 8], 20);
#pragma unroll
                    for (int i = 0; i < 2; i++)
                        wmma::mma_sync(acc[i][j], af[i], bf, acc[i][j]);
                }
            }
            __syncthreads();
        }
#pragma unroll
        for (int i = 0; i < 2; i++)
#pragma unroll
            for (int j = 0; j < 4; j++) {
#pragma unroll
                for (int t = 0; t < acc[i][j].num_elements; t++) acc[i][j].x[t] *= 0.0625f;
                wmma::store_matrix_sync(&sS[(i * 16) * 516 + wid * 64 + j * 16],
                                        acc[i][j], 516, wmma::mem_row_major);
            }
    }
    __syncthreads();

    // ---- softmax: 8 warps x 4 rows (fast exp via MUFU.EX2) ----
#pragma unroll
    for (int rr = 0; rr < 4; rr++) {
        int r = wid * 4 + rr;
        float mx = -1e30f;
        for (int c = lane; c < 512; c += 32) mx = fmaxf(mx, sS[r * 516 + c]);
#pragma unroll
        for (int o = 16; o; o >>= 1) mx = fmaxf(mx, __shfl_xor_sync(0xffffffffu, mx, o));
        float sum = 0.f;
        for (int c = lane; c < 512; c += 32) {
            float e = __expf(sS[r * 516 + c] - mx);
            sS[r * 516 + c] = e;
            sum += e;
        }
#pragma unroll
        for (int o = 16; o; o >>= 1) sum += __shfl_xor_sync(0xffffffffu, sum, o);
        float inv = 1.f / sum;
        for (int c = lane; c < 512; c += 32) sS[r * 516 + c] *= inv;
    }
    __syncthreads();   // scores final; sK region free for per-warp V tiles

    // ---- phase 2: ctx = P @ V; warp tile 32 rows x 32 cols ----
    {
        float* sVw = sK + wid * (2 * 576);   // 2 buffers of 16x36

        wmma::fragment<wmma::accumulator, 16, 16, 8, float> acc2[2][2];
#pragma unroll
        for (int i = 0; i < 2; i++)
#pragma unroll
            for (int j = 0; j < 2; j++) wmma::fill_fragment(acc2[i][j], 0.f);

        auto stage_v = [&](int kc) {
            float* dst = sVw + (kc & 1) * 576;
#pragma unroll
            for (int it = 0; it < 4; it++) {
                int lin = lane + it * 32;
                int r = lin >> 3, c4 = (lin & 7) * 4;
                cpa16(&dst[r * 36 + c4],
                      &v[base + (size_t)(kc * 16 + r) * KD + wid * 32 + c4]);
            }
        };

        stage_v(0); CPA_COMMIT();

        for (int kc = 0; kc < 32; kc++) {
            if (kc + 1 < 32) { stage_v(kc + 1); CPA_COMMIT(); CPA_WAIT1(); }
            else             { CPA_WAIT0(); }
            __syncwarp();
            float* sVc = sVw + (kc & 1) * 576;
#pragma unroll
            for (int kk = 0; kk < 2; kk++) {
                wmma::fragment<wmma::matrix_a, 16, 16, 8, wmma::precision::tf32, wmma::row_major> af[2];
#pragma unroll
                for (int i = 0; i < 2; i++)
                    wmma::load_matrix_sync(af[i], &sS[(i * 16) * 516 + kc * 16 + kk * 8], 516);
#pragma unroll
                for (int j = 0; j < 2; j++) {
                    wmma::fragment<wmma::matrix_b, 16, 16, 8, wmma::precision::tf32, wmma::row_major> bf;
                    wmma::load_matrix_sync(bf, &sVc[(kk * 8) * 36 + j * 16], 36);
#pragma unroll
                    for (int i = 0; i < 2; i++)
                        wmma::mma_sync(acc2[i][j], af[i], bf, acc2[i][j]);
                }
            }
            __syncwarp();
        }

        const int b_ = bwh >> 4, w = (bwh >> 1) & 7, h = bwh & 1;
        const size_t tok0 = (size_t)b_ * SS + w * WINS + m0;
#pragma unroll
        for (int i = 0; i < 2; i++)
#pragma unroll
            for (int j = 0; j < 2; j++) {
                size_t row = tok0 + i * 16;
                int col = h * KD + wid * 32 + j * 16;
                wmma::store_matrix_sync(&ctx[row * (HH * KD) + col], acc2[i][j],
                                        HH * KD, wmma::mem_row_major);
            }
    }
}

// ---------------- launch ----------------------------------------------------
extern "C" void kernel_launch(void* const* d_in, const int* in_sizes, int n_in,
                              void* d_out, int out_size)
{
    const float* x    = (const float*)d_in[0];
    const float* Wq   = (const float*)d_in[1];
    const float* bq   = (const float*)d_in[2];
    const float* Wk   = (const float*)d_in[3];
    const float* bk   = (const float*)d_in[4];
    const float* Wv   = (const float*)d_in[5];
    const float* bv   = (const float*)d_in[6];
    const float* Wo   = (const float*)d_in[7];
    const float* bo   = (const float*)d_in[8];
    const float* ln1g = (const float*)d_in[9];
    const float* ln1b = (const float*)d_in[10];
    const float* W1   = (const float*)d_in[11];
    const float* b1   = (const float*)d_in[12];
    const float* W2   = (const float*)d_in[13];
    const float* b2   = (const float*)d_in[14];
    const float* ln2g = (const float*)d_in[15];
    const float* ln2b = (const float*)d_in[16];

    float *q, *k, *v, *ctx, *y, *hbuf;
    cudaGetSymbolAddress((void**)&q,    g_q);
    cudaGetSymbolAddress((void**)&k,    g_k);
    cudaGetSymbolAddress((void**)&v,    g_v);
    cudaGetSymbolAddress((void**)&ctx,  g_ctx);
    cudaGetSymbolAddress((void**)&y,    g_y);
    cudaGetSymbolAddress((void**)&hbuf, g_h);

    cudaFuncSetAttribute(attn_tc,    cudaFuncAttributeMaxDynamicSharedMemorySize, SMEM_ATTN);
    cudaFuncSetAttribute(qkv_tc,     cudaFuncAttributeMaxDynamicSharedMemorySize, GEMM_SMEM);
    cudaFuncSetAttribute(gemm_tc<1>, cudaFuncAttributeMaxDynamicSharedMemorySize, GEMM_SMEM);
    cudaFuncSetAttribute(gemm_tc<3>, cudaFuncAttributeMaxDynamicSharedMemorySize, GEMM_SMEM);

    dim3 blk(256);

    // fused QKV projections (scatter into [b,w,h,s,k]); N=512 -> 2 n-tiles
    qkv_tc<<<dim3(2, 256, 3), blk, GEMM_SMEM>>>(x, Wq, Wk, Wv, bq, bk, bv);

    // windowed attention
    attn_tc<<<dim3(16, 128), blk, SMEM_ATTN>>>(q, k, v, ctx);

    // output projection fused with residual+LN1: y = LN(ctx@Wo + bo + x)
    gemm_tc<3><<<dim3(1, 256), blk, GEMM_SMEM>>>(ctx, Wo, bo, y, DD, HH * KD,
                                                 x, ln1g, ln1b);

    // FFN: h = relu(y@W1 + b1)
    gemm_tc<1><<<dim3(4, 256), blk, GEMM_SMEM>>>(y, W1, b1, hbuf, DFF, DD,
                                                 nullptr, nullptr, nullptr);
    // out = LN(h@W2 + b2 + y)
    gemm_tc<3><<<dim3(1, 256), blk, GEMM_SMEM>>>(hbuf, W2, b2, (float*)d_out, DD, DFF,
                                                 y, ln2g, ln2b);
}

// round 16
// speedup vs baseline: 1.7580x; 1.0636x over previous
#include <cuda_runtime.h>
#include <cstdint>
#include <mma.h>
using namespace nvcuda;

// Problem constants
#define BB   8
#define SS   4096
#define DD   256
#define NW   8
#define WINS 512
#define HH   2
#define KD   256
#define DFF  1024
#define MTOK (BB*SS)          // 32768 tokens

// ---------------- device scratch (static allocation; no cudaMalloc) -------
__device__ float g_q  [(size_t)BB*SS*HH*KD];   // [b,w,h,s,k]
__device__ float g_k  [(size_t)BB*SS*HH*KD];
__device__ float g_v  [(size_t)BB*SS*HH*KD];
__device__ float g_ctx[(size_t)BB*SS*HH*KD];   // [token, h*K+k]
__device__ float g_y  [(size_t)MTOK*DD];       // post-LN1
__device__ float g_h  [(size_t)MTOK*DFF];      // FFN hidden

// ---------------- cp.async helpers -----------------------------------------
__device__ __forceinline__ void cpa16(float* smem, const float* g) {
    unsigned s = (unsigned)__cvta_generic_to_shared(smem);
    asm volatile("cp.async.cg.shared.global [%0], [%1], 16;" :: "r"(s), "l"(g));
}
#define CPA_COMMIT() asm volatile("cp.async.commit_group;")
#define CPA_WAIT2()  asm volatile("cp.async.wait_group 2;")
#define CPA_WAIT1()  asm volatile("cp.async.wait_group 1;")
#define CPA_WAIT0()  asm volatile("cp.async.wait_group 0;")

// ---------------- tf32 wmma GEMM: block 128x256, warp tile 64x64 ------------
// C[M,N] = A[M,Kd] @ B[Kd,N] + bias[N]
// EPI: 0 plain, 1 relu, 2 qkv-scatter, 3 residual+LayerNorm (needs N==256)
// 8 warps in 2x4 grid; 3-stage cp.async; 1 CTA/SM (155KB smem).
#define GSTG  12928                   // floats/stage: A 128*36 + B 32*260
#define GEMM_SMEM (3*GSTG*4)          // 155,136 B

template<int EPI>
__device__ __forceinline__
void gemm_body(const float* __restrict__ A, const float* __restrict__ Bm,
               const float* __restrict__ bias, float* __restrict__ C,
               int N, int Kd, float* sg,
               const float* __restrict__ resid,
               const float* __restrict__ lng,
               const float* __restrict__ lnb)
{
    const int m0 = blockIdx.y * 128;
    const int n0 = blockIdx.x * 256;
    const int tid = threadIdx.x;
    const int wid = tid >> 5;
    const int lane = tid & 31;
    const int wr = wid >> 2;     // 0..1 -> 64-row group
    const int wc = wid & 3;      // 0..3 -> 64-col group

    const int ar = tid >> 3, ac = (tid & 7) * 4;     // A: 128x32, 4 float4/thr

    wmma::fragment<wmma::accumulator, 16, 16, 8, float> acc[4][4];
#pragma unroll
    for (int i = 0; i < 4; i++)
#pragma unroll
        for (int j = 0; j < 4; j++) wmma::fill_fragment(acc[i][j], 0.f);

    const int nk = Kd >> 5;

    auto load_stage = [&](int s, int k0) {
        float* As = sg + s * GSTG;
        float* Bs = As + 4608;
#pragma unroll
        for (int it = 0; it < 4; it++)
            cpa16(&As[(ar + it * 32) * 36 + ac],
                  &A[(size_t)(m0 + ar + it * 32) * Kd + k0 + ac]);
#pragma unroll
        for (int it = 0; it < 8; it++) {             // B: 32x256, 8 float4/thr
            int lin = tid + it * 256;
            int r = lin >> 6, c = (lin & 63) * 4;
            cpa16(&Bs[r * 260 + c],
                  &Bm[(size_t)(k0 + r) * N + n0 + c]);
        }
    };

    load_stage(0, 0);  CPA_COMMIT();
    load_stage(1, 32); CPA_COMMIT();
    load_stage(2, 64); CPA_COMMIT();

    for (int c = 0; c < nk; c++) {
        int rem = nk - 1 - c;
        if (rem >= 2) { CPA_WAIT2(); } else if (rem == 1) { CPA_WAIT1(); } else { CPA_WAIT0(); }
        __syncthreads();
        float* As = sg + (c % 3) * GSTG;
        float* Bs = As + 4608;
#pragma unroll
        for (int kk = 0; kk < 4; kk++) {
            wmma::fragment<wmma::matrix_a, 16, 16, 8, wmma::precision::tf32, wmma::row_major> af[4];
#pragma unroll
            for (int i = 0; i < 4; i++)
                wmma::load_matrix_sync(af[i], &As[(wr * 64 + i * 16) * 36 + kk * 8], 36);
#pragma unroll
            for (int j = 0; j < 4; j++) {
                wmma::fragment<wmma::matrix_b, 16, 16, 8, wmma::precision::tf32, wmma::row_major> bf;
                wmma::load_matrix_sync(bf, &Bs[(kk * 8) * 260 + wc * 64 + j * 16], 260);
#pragma unroll
                for (int i = 0; i < 4; i++)
                    wmma::mma_sync(acc[i][j], af[i], bf, acc[i][j]);
            }
        }
        __syncthreads();
        if (c + 3 < nk) { load_stage(c % 3, (c + 3) * 32); CPA_COMMIT(); }
    }

    // epilogue: two 64-row halves staged through smem (64 x 264)
    float* se = sg;
#pragma unroll
    for (int h = 0; h < 2; h++) {
        if (wr == h) {
#pragma unroll
            for (int i = 0; i < 4; i++)
#pragma unroll
                for (int j = 0; j < 4; j++)
                    wmma::store_matrix_sync(&se[(i * 16) * 264 + wc * 64 + j * 16],
                                            acc[i][j], 264, wmma::mem_row_major);
        }
        __syncthreads();
        if (EPI == 3) {
            // residual + LayerNorm over full 256-wide rows; warp w -> rows w*8..w*8+7
#pragma unroll
            for (int rr = 0; rr < 8; rr++) {
                int r = wid * 8 + rr;                // 0..63 within half
                size_t row = (size_t)(m0 + h * 64 + r);
                float vv[8];
                float s = 0.f;
#pragma unroll
                for (int j = 0; j < 8; j++) {
                    int cc = lane + j * 32;
                    vv[j] = se[r * 264 + cc] + bias[cc] + resid[row * DD + cc];
                    s += vv[j];
                }
#pragma unroll
                for (int o = 16; o; o >>= 1) s += __shfl_xor_sync(0xffffffffu, s, o);
                float mu = s * (1.f / 256.f);
                float vs = 0.f;
#pragma unroll
                for (int j = 0; j < 8; j++) {
                    float d = vv[j] - mu;
                    vs += d * d;
                }
#pragma unroll
                for (int o = 16; o; o >>= 1) vs += __shfl_xor_sync(0xffffffffu, vs, o);
                float inv = rsqrtf(vs * (1.f / 256.f) + 1e-3f);
#pragma unroll
                for (int j = 0; j < 8; j++) {
                    int cc = lane + j * 32;
                    C[row * DD + cc] = (vv[j] - mu) * inv * lng[cc] + lnb[cc];
                }
            }
        } else {
#pragma unroll
            for (int it = 0; it < 16; it++) {
                int lin = tid + it * 256;           // 0..4095 quads (64x256 elems)
                int r = lin >> 6, c4 = (lin & 63) * 4;
                int row = m0 + h * 64 + r, col = n0 + c4;
                float4 cv;
                cv.x = se[r * 264 + c4 + 0] + bias[col + 0];
                cv.y = se[r * 264 + c4 + 1] + bias[col + 1];
                cv.z = se[r * 264 + c4 + 2] + bias[col + 2];
                cv.w = se[r * 264 + c4 + 3] + bias[col + 3];
                if (EPI == 1) {
                    cv.x = fmaxf(cv.x, 0.f); cv.y = fmaxf(cv.y, 0.f);
                    cv.z = fmaxf(cv.z, 0.f); cv.w = fmaxf(cv.w, 0.f);
                }
                if (EPI == 2) {
                    int b_ = row >> 12, sgx = row & 4095;
                    int w  = sgx >> 9,  sl = sgx & 511;
                    int hh = col >> 8,  kd = col & 255;
                    size_t idx = (((size_t)((b_ * NW + w) * HH + hh)) * WINS + sl) * KD + kd;
                    *(float4*)&C[idx] = cv;
                } else {
                    *(float4*)&C[(size_t)row * N + col] = cv;
                }
            }
        }
        __syncthreads();
    }
}

template<int EPI>
__global__ __launch_bounds__(256, 1)
void gemm_tc(const float* __restrict__ A, const float* __restrict__ Bm,
             const float* __restrict__ bias, float* __restrict__ C,
             int N, int Kd,
             const float* resid, const float* lng, const float* lnb)
{
    extern __shared__ float sg[];
    gemm_body<EPI>(A, Bm, bias, C, N, Kd, sg, resid, lng, lnb);
}

// fused QKV: grid.z selects {q,k,v}
__global__ __launch_bounds__(256, 1)
void qkv_tc(const float* __restrict__ x,
            const float* __restrict__ Wq, const float* __restrict__ Wk,
            const float* __restrict__ Wv,
            const float* __restrict__ bq, const float* __restrict__ bk,
            const float* __restrict__ bv)
{
    extern __shared__ float sg[];
    int z = blockIdx.z;
    const float* Bm  = (z == 0) ? Wq : (z == 1) ? Wk : Wv;
    const float* bia = (z == 0) ? bq : (z == 1) ? bk : bv;
    float* C = (z == 0) ? g_q : (z == 1) ? g_k : g_v;
    gemm_body<2>(x, Bm, bia, C, HH * KD, DD, sg, nullptr, nullptr, nullptr);
}

// ---------------- windowed attention (tensor-core, 32-query tiles) ----------
// grid: (WIN/32 = 16, B*NW*H = 128), 256 threads (8 warps)
// smem: sS[32][516] | per-warp K/V tiles (8 warps x 2 bufs x 64x12 floats)
// Phase 1: warp-private double-buffered cp.async K chunks, Q fragments
// straight from gmem (L1-resident) -> NO block barriers in phase 1.
#define KBUF 768                       // floats per buffer: 64 x 12
#define SMEM_ATTN ((32*516 + 8*2*KBUF) * 4)   // 115,200 B

__global__ __launch_bounds__(256, 2)
void attn_tc(const float* __restrict__ q, const float* __restrict__ k,
             const float* __restrict__ v, float* __restrict__ ctx)
{
    extern __shared__ float sm[];
    float* sS  = sm;                     // 32 x 516
    float* sK  = sm + 32 * 516;          // warp tiles

    const int bwh = blockIdx.y;
    const int m0  = blockIdx.x * 32;
    const size_t base = (size_t)bwh * WINS * KD;
    const int tid = threadIdx.x;
    const int wid = tid >> 5;
    const int lane = tid & 31;

    // ---- phase 1: S = Q K^T / 16; warp owns 64 keys, streams 8-dim chunks --
    {
        float* sKw = sK + wid * (2 * KBUF);

        wmma::fragment<wmma::accumulator, 16, 16, 8, float> acc[2][4];
#pragma unroll
        for (int i = 0; i < 2; i++)
#pragma unroll
            for (int j = 0; j < 4; j++) wmma::fill_fragment(acc[i][j], 0.f);

        auto stage_k = [&](int kc) {
            float* dst = sKw + (kc & 1) * KBUF;
#pragma unroll
            for (int it = 0; it < 4; it++) {
                int lin = lane + it * 32;            // 0..127
                int r = lin >> 1, seg = (lin & 1) * 4;
                cpa16(&dst[r * 12 + seg],
                      &k[base + (size_t)(wid * 64 + r) * KD + kc * 8 + seg]);
            }
        };

        stage_k(0); CPA_COMMIT();

        for (int kc = 0; kc < 32; kc++) {            // 8-dim chunks of KD
            if (kc + 1 < 32) { stage_k(kc + 1); CPA_COMMIT(); CPA_WAIT1(); }
            else             { CPA_WAIT0(); }
            __syncwarp();
            float* cur = sKw + (kc & 1) * KBUF;
            wmma::fragment<wmma::matrix_a, 16, 16, 8, wmma::precision::tf32, wmma::row_major> af[2];
#pragma unroll
            for (int i = 0; i < 2; i++)
                wmma::load_matrix_sync(af[i], &q[base + (size_t)(m0 + i * 16) * KD + kc * 8], KD);
#pragma unroll
            for (int j = 0; j < 4; j++) {
                wmma::fragment<wmma::matrix_b, 16, 16, 8, wmma::precision::tf32, wmma::col_major> bf;
                wmma::load_matrix_sync(bf, &cur[(j * 16) * 12], 12);
#pragma unroll
                for (int i = 0; i < 2; i++)
                    wmma::mma_sync(acc[i][j], af[i], bf, acc[i][j]);
            }
            __syncwarp();
        }
        // scale + dump to score strip
#pragma unroll
        for (int i = 0; i < 2; i++)
#pragma unroll
            for (int j = 0; j < 4; j++) {
#pragma unroll
                for (int t = 0; t < acc[i][j].num_elements; t++) acc[i][j].x[t] *= 0.0625f;
                wmma::store_matrix_sync(&sS[(i * 16) * 516 + wid * 64 + j * 16],
                                        acc[i][j], 516, wmma::mem_row_major);
            }
    }
    __syncthreads();

    // ---- softmax: 8 warps x 4 rows (fast exp via MUFU.EX2) ----
#pragma unroll
    for (int rr = 0; rr < 4; rr++) {
        int r = wid * 4 + rr;
        float mx = -1e30f;
        for (int c = lane; c < 512; c += 32) mx = fmaxf(mx, sS[r * 516 + c]);
#pragma unroll
        for (int o = 16; o; o >>= 1) mx = fmaxf(mx, __shfl_xor_sync(0xffffffffu, mx, o));
        float sum = 0.f;
        for (int c = lane; c < 512; c += 32) {
            float e = __expf(sS[r * 516 + c] - mx);
            sS[r * 516 + c] = e;
            sum += e;
        }
#pragma unroll
        for (int o = 16; o; o >>= 1) sum += __shfl_xor_sync(0xffffffffu, sum, o);
        float inv = 1.f / sum;
        for (int c = lane; c < 512; c += 32) sS[r * 516 + c] *= inv;
    }
    __syncthreads();   // scores final; sK region free for per-warp V tiles

    // ---- phase 2: ctx = P @ V; warp tile 32 rows x 32 cols ----
    {
        float* sVw = sK + wid * (2 * 576);   // 2 buffers of 16x36

        wmma::fragment<wmma::accumulator, 16, 16, 8, float> acc2[2][2];
#pragma unroll
        for (int i = 0; i < 2; i++)
#pragma unroll
            for (int j = 0; j < 2; j++) wmma::fill_fragment(acc2[i][j], 0.f);

        auto stage_v = [&](int kc) {
            float* dst = sVw + (kc & 1) * 576;
#pragma unroll
            for (int it = 0; it < 4; it++) {
                int lin = lane + it * 32;
                int r = lin >> 3, c4 = (lin & 7) * 4;
                cpa16(&dst[r * 36 + c4],
                      &v[base + (size_t)(kc * 16 + r) * KD + wid * 32 + c4]);
            }
        };

        stage_v(0); CPA_COMMIT();

        for (int kc = 0; kc < 32; kc++) {
            if (kc + 1 < 32) { stage_v(kc + 1); CPA_COMMIT(); CPA_WAIT1(); }
            else             { CPA_WAIT0(); }
            __syncwarp();
            float* sVc = sVw + (kc & 1) * 576;
#pragma unroll
            for (int kk = 0; kk < 2; kk++) {
                wmma::fragment<wmma::matrix_a, 16, 16, 8, wmma::precision::tf32, wmma::row_major> af[2];
#pragma unroll
                for (int i = 0; i < 2; i++)
                    wmma::load_matrix_sync(af[i], &sS[(i * 16) * 516 + kc * 16 + kk * 8], 516);
#pragma unroll
                for (int j = 0; j < 2; j++) {
                    wmma::fragment<wmma::matrix_b, 16, 16, 8, wmma::precision::tf32, wmma::row_major> bf;
                    wmma::load_matrix_sync(bf, &sVc[(kk * 8) * 36 + j * 16], 36);
#pragma unroll
                    for (int i = 0; i < 2; i++)
                        wmma::mma_sync(acc2[i][j], af[i], bf, acc2[i][j]);
                }
            }
            __syncwarp();
        }

        const int b_ = bwh >> 4, w = (bwh >> 1) & 7, h = bwh & 1;
        const size_t tok0 = (size_t)b_ * SS + w * WINS + m0;
#pragma unroll
        for (int i = 0; i < 2; i++)
#pragma unroll
            for (int j = 0; j < 2; j++) {
                size_t row = tok0 + i * 16;
                int col = h * KD + wid * 32 + j * 16;
                wmma::store_matrix_sync(&ctx[row * (HH * KD) + col], acc2[i][j],
                                        HH * KD, wmma::mem_row_major);
            }
    }
}

// ---------------- launch ----------------------------------------------------
extern "C" void kernel_launch(void* const* d_in, const int* in_sizes, int n_in,
                              void* d_out, int out_size)
{
    const float* x    = (const float*)d_in[0];
    const float* Wq   = (const float*)d_in[1];
    const float* bq   = (const float*)d_in[2];
    const float* Wk   = (const float*)d_in[3];
    const float* bk   = (const float*)d_in[4];
    const float* Wv   = (const float*)d_in[5];
    const float* bv   = (const float*)d_in[6];
    const float* Wo   = (const float*)d_in[7];
    const float* bo   = (const float*)d_in[8];
    const float* ln1g = (const float*)d_in[9];
    const float* ln1b = (const float*)d_in[10];
    const float* W1   = (const float*)d_in[11];
    const float* b1   = (const float*)d_in[12];
    const float* W2   = (const float*)d_in[13];
    const float* b2   = (const float*)d_in[14];
    const float* ln2g = (const float*)d_in[15];
    const float* ln2b = (const float*)d_in[16];

    float *q, *k, *v, *ctx, *y, *hbuf;
    cudaGetSymbolAddress((void**)&q,    g_q);
    cudaGetSymbolAddress((void**)&k,    g_k);
    cudaGetSymbolAddress((void**)&v,    g_v);
    cudaGetSymbolAddress((void**)&ctx,  g_ctx);
    cudaGetSymbolAddress((void**)&y,    g_y);
    cudaGetSymbolAddress((void**)&hbuf, g_h);

    cudaFuncSetAttribute(attn_tc,    cudaFuncAttributeMaxDynamicSharedMemorySize, SMEM_ATTN);
    cudaFuncSetAttribute(qkv_tc,     cudaFuncAttributeMaxDynamicSharedMemorySize, GEMM_SMEM);
    cudaFuncSetAttribute(gemm_tc<1>, cudaFuncAttributeMaxDynamicSharedMemorySize, GEMM_SMEM);
    cudaFuncSetAttribute(gemm_tc<3>, cudaFuncAttributeMaxDynamicSharedMemorySize, GEMM_SMEM);

    dim3 blk(256);

    // fused QKV projections (scatter into [b,w,h,s,k]); N=512 -> 2 n-tiles
    qkv_tc<<<dim3(2, 256, 3), blk, GEMM_SMEM>>>(x, Wq, Wk, Wv, bq, bk, bv);

    // windowed attention
    attn_tc<<<dim3(16, 128), blk, SMEM_ATTN>>>(q, k, v, ctx);

    // output projection fused with residual+LN1: y = LN(ctx@Wo + bo + x)
    gemm_tc<3><<<dim3(1, 256), blk, GEMM_SMEM>>>(ctx, Wo, bo, y, DD, HH * KD,
                                                 x, ln1g, ln1b);

    // FFN: h = relu(y@W1 + b1)
    gemm_tc<1><<<dim3(4, 256), blk, GEMM_SMEM>>>(y, W1, b1, hbuf, DFF, DD,
                                                 nullptr, nullptr, nullptr);
    // out = LN(h@W2 + b2 + y)
    gemm_tc<3><<<dim3(1, 256), blk, GEMM_SMEM>>>(hbuf, W2, b2, (float*)d_out, DD, DFF,
                                                 y, ln2g, ln2b);
}